// round 14
// baseline (speedup 1.0000x reference)
#include <cuda_runtime.h>
#include <cuda_fp16.h>
#include <cstdint>

// VectorQuantizer: single-pass fp16 mma.sync screening (m16n8k16, fp32 acc)
// + sorted top-4 candidates + exact fp32 rerank.
// R11: cooperative quad rerank (4 lanes per candidate row, x staged in smem).

#define D      64
#define K      1024
#define MTILE  128        // points per CTA (8 warps x 16 rows)
#define WTILE  64         // codewords per tile
#define KT     (K / WTILE)
#define BLOCK  256
#define HW     1024       // d-stride inside x

// ---- smem layout (bytes) ----
#define OFF_Y   0                 // 128 x 128B fp16   (reused by XS after loop)
#define OFF_W   16384             // 2 bufs x 8KB      (reused by XS after loop)
#define W_BUF   8192
#define OFF_WN  32768             // 1024 fp32 norms   (reused by XS after loop)
#define OFF_XN  36864             // 2 x 128 fp32 partial ||x||^2
#define OFF_TOP 37888             // 128 x uint4 (sorted top-4 keys)  [live in rerank]
#define OFF_RED 39936             // 512 fp32 candidate scores (rerank)
#define OFF_IDX 41984             // 128 int
#define SMEM_TOTAL 42496

// rerank staging: fp32 latents, stride 68 floats (272B), 128*68*4 = 34816 B at 0
#define OFF_XS   0
#define XS_STRIDE 68

#define SW(o) ((o) ^ (((o) >> 3) & 0x70))

// ---- global scratch: swizzled fp16 codebook tiles + norms ----
__device__ __align__(1024) static char  g_wsw[KT][WTILE * 128];
__device__ __align__(16)   static float g_wn[K];

static __device__ __forceinline__ uint32_t smem_u32(const void* p) {
    uint32_t a;
    asm("{ .reg .u64 t; cvta.to.shared.u64 t, %1; cvt.u32.u64 %0, t; }" : "=r"(a) : "l"(p));
    return a;
}
static __device__ __forceinline__ void cp16(uint32_t saddr, const void* g) {
    asm volatile("cp.async.cg.shared.global [%0], [%1], 16;"
                 :: "r"(saddr), "l"((size_t)__cvta_generic_to_global(g)) : "memory");
}
static __device__ __forceinline__ void ldsm4(uint32_t r[4], uint32_t addr) {
    asm volatile("ldmatrix.sync.aligned.m8n8.x4.shared.b16 {%0,%1,%2,%3}, [%4];"
                 : "=r"(r[0]), "=r"(r[1]), "=r"(r[2]), "=r"(r[3]) : "r"(addr));
}
static __device__ __forceinline__ void mma16816(float c[4], const uint32_t a[4],
                                                uint32_t b0, uint32_t b1) {
    asm volatile("mma.sync.aligned.m16n8k16.row.col.f32.f16.f16.f32 "
                 "{%0,%1,%2,%3}, {%4,%5,%6,%7}, {%8,%9}, {%0,%1,%2,%3};"
                 : "+f"(c[0]), "+f"(c[1]), "+f"(c[2]), "+f"(c[3])
                 : "r"(a[0]), "r"(a[1]), "r"(a[2]), "r"(a[3]), "r"(b0), "r"(b1));
}
static __device__ __forceinline__ uint32_t umn(uint32_t a, uint32_t b) { return a < b ? a : b; }
static __device__ __forceinline__ uint32_t umx(uint32_t a, uint32_t b) { return a > b ? a : b; }

// scores >= ~1 -> raw float bits order as u32. 13 mantissa bits + 10 index bits.
static __device__ __forceinline__ uint32_t fkey(float v, int col) {
    return (__float_as_uint(v) & 0xFFFFFC00u) | (uint32_t)col;
}
static __device__ __forceinline__ void mrg2(uint32_t& o1, uint32_t& o2,
                                            uint32_t a1, uint32_t a2,
                                            uint32_t b1, uint32_t b2) {
    o1 = umn(a1, b1);
    o2 = umn(umx(a1, b1), umn(a2, b2));
}
// sorted top-2 of 8 keys
static __device__ __forceinline__ void top2of8(const uint32_t k[8],
                                               uint32_t& t1, uint32_t& t2) {
    uint32_t a1 = umn(k[0], k[1]), a2 = umx(k[0], k[1]);
    uint32_t b1 = umn(k[2], k[3]), b2 = umx(k[2], k[3]);
    uint32_t c1 = umn(k[4], k[5]), c2 = umx(k[4], k[5]);
    uint32_t d1 = umn(k[6], k[7]), d2 = umx(k[6], k[7]);
    uint32_t e1, e2, f1, f2;
    mrg2(e1, e2, a1, a2, b1, b2);
    mrg2(f1, f2, c1, c2, d1, d2);
    mrg2(t1, t2, e1, e2, f1, f2);
}
// insert sorted pair (t1<=t2) into sorted-4 r[], keep lowest 4
static __device__ __forceinline__ void ins2into4(uint32_t r[4], uint32_t t1, uint32_t t2) {
    uint32_t m0 = r[0];
    uint32_t m1 = r[1];
    uint32_t m2 = umn(r[2], t2);
    uint32_t m3 = umn(r[3], t1);
    uint32_t s0 = umn(m0, m2), s2 = umx(m0, m2);
    uint32_t s1 = umn(m1, m3), s3 = umx(m1, m3);
    r[0] = umn(s0, s1); r[1] = umx(s0, s1);
    r[2] = umn(s2, s3); r[3] = umx(s2, s3);
}
// merge two sorted-4 lists, keep lowest 4
static __device__ __forceinline__ void mrg4(uint32_t r[4], const uint32_t b[4]) {
    uint32_t m0 = umn(r[0], b[3]);
    uint32_t m1 = umn(r[1], b[2]);
    uint32_t m2 = umn(r[2], b[1]);
    uint32_t m3 = umn(r[3], b[0]);
    uint32_t s0 = umn(m0, m2), s2 = umx(m0, m2);
    uint32_t s1 = umn(m1, m3), s3 = umx(m1, m3);
    r[0] = umn(s0, s1); r[1] = umx(s0, s1);
    r[2] = umn(s2, s3); r[3] = umx(s2, s3);
}

// ---------------- pre-kernel: convert codebook once ----------------
__global__ __launch_bounds__(256)
void vq_prep_kernel(const float* __restrict__ w)
{
    const int gid = blockIdx.x * 256 + threadIdx.x;   // 128 blocks -> 32768 threads
    {
        const int i  = gid;                           // pair index
        const int kr = i >> 5;                        // codeword 0..1023
        const int p  = i & 31;                        // pair within row
        float2 v = ((const float2*)w)[i];
        __half h0 = __float2half_rn(v.x), h1 = __float2half_rn(v.y);
        const int kt = kr >> 6, pr = kr & 63;
        uint32_t o = SW((uint32_t)(pr * 128 + p * 4));
        *(__half2*)(g_wsw[kt] + o) = __halves2half2(h0, h1);
    }
    if (gid < K) {
        const float4* wr = (const float4*)(w + (size_t)gid * D);
        float s = 0.0f;
#pragma unroll
        for (int q = 0; q < D / 4; q++) {
            float4 f = wr[q];
            s = fmaf(f.x, f.x, s); s = fmaf(f.y, f.y, s);
            s = fmaf(f.z, f.z, s); s = fmaf(f.w, f.w, s);
        }
        g_wn[gid] = s;
    }
}

// ---------------- main kernel ----------------
__global__ __launch_bounds__(BLOCK, 4)
void vq_hmma_kernel(const float* __restrict__ x,
                    const float* __restrict__ w,
                    float* __restrict__ out)
{
    extern __shared__ char sm[];
    const uint32_t smb = smem_u32(sm);
    const int tid  = threadIdx.x;
    const int lane = tid & 31;
    const int warp = tid >> 5;

    const int n0   = blockIdx.x * MTILE;
    const int bimg = n0 >> 10;
    const int hw0  = n0 & (HW - 1);

    // ---- prefetch: norms + tiles 0 and 1 (8KB each = 2 cp16/thread) ----
    cp16(smb + OFF_WN + tid * 16, g_wn + tid * 4);
#pragma unroll
    for (int i = 0; i < 2; i++) {
        int off = (tid + i * BLOCK) * 16;
        cp16(smb + OFF_W + off, g_wsw[0] + off);
    }
    asm volatile("cp.async.commit_group;" ::: "memory");
#pragma unroll
    for (int i = 0; i < 2; i++) {
        int off = (tid + i * BLOCK) * 16;
        cp16(smb + OFF_W + W_BUF + off, g_wsw[1] + off);
    }
    asm volatile("cp.async.commit_group;" ::: "memory");

    // ---- build Y = fp16(-2x) swizzled + partial ||x||^2 ----
    {
        const int p  = tid & 127;
        const int d0 = (tid >> 7) * 32;
        const float* xp = x + (size_t)bimg * D * HW + hw0 + p;
        char* y = sm + OFF_Y;
        const uint32_t rb = (uint32_t)p * 128;
        float xs = 0.0f;
#pragma unroll
        for (int dd = 0; dd < 32; dd += 2) {
            const int d = d0 + dd;
            float xv0 = xp[(size_t)d * HW];
            float xv1 = xp[(size_t)(d + 1) * HW];
            xs = fmaf(xv0, xv0, xs);
            xs = fmaf(xv1, xv1, xs);
            __half h0 = __float2half_rn(-2.0f * xv0);
            __half h1 = __float2half_rn(-2.0f * xv1);
            uint32_t o = SW(rb + (uint32_t)d * 2);
            *(__half2*)(y + o) = __halves2half2(h0, h1);
        }
        ((float*)(sm + OFF_XN))[(tid >> 7) * 128 + p] = xs;
    }
    __syncthreads();   // Y + xn partials visible

    // ---- per-lane row norms: xn + 1 ----
    float xnA, xnB;
    {
        const float* xpart = (const float*)(sm + OFF_XN);
        const int r0 = warp * 16 + (lane >> 2);
        xnA = xpart[r0] + xpart[128 + r0] + 1.0f;
        xnB = xpart[r0 + 8] + xpart[128 + r0 + 8] + 1.0f;
    }

    // ---- A fragments (this warp's 16 points x 64 d) in regs ----
    uint32_t ahi[4][4];
    const int lr = lane & 7;
    const int mI = lane >> 3;
    {
        const uint32_t arow = (uint32_t)(warp * 16 + (mI & 1) * 8 + lr) * 128;
#pragma unroll
        for (int kc = 0; kc < 4; kc++) {
            uint32_t ch = (uint32_t)((kc * 2 + (mI >> 1)) ^ lr) * 16;
            ldsm4(ahi[kc], smb + OFF_Y + arow + ch);
        }
    }

    const uint32_t offb0 = (uint32_t)lr * 128 + (uint32_t)(mI ^ lr) * 16;       // k-chunks 0-3
    const uint32_t offb1 = (uint32_t)lr * 128 + (uint32_t)((4 + mI) ^ lr) * 16; // k-chunks 4-7
    const float* wn = (const float*)(sm + OFF_WN);

    uint32_t rA[4] = {0xFFFFFFFFu, 0xFFFFFFFFu, 0xFFFFFFFFu, 0xFFFFFFFFu};
    uint32_t rB[4] = {0xFFFFFFFFu, 0xFFFFFFFFu, 0xFFFFFFFFu, 0xFFFFFFFFu};

#pragma unroll 1
    for (int kt = 0; kt < KT; kt++) {
        const int buf = kt & 1;
        if (kt < KT - 1) asm volatile("cp.async.wait_group 1;" ::: "memory");
        else             asm volatile("cp.async.wait_group 0;" ::: "memory");
        __syncthreads();   // tile visible; prior compute on buf done

        const uint32_t gb = smb + OFF_W + (uint32_t)buf * W_BUF;

#pragma unroll
        for (int g = 0; g < WTILE / 32; g++) {
            const uint32_t th = gb + (uint32_t)g * 32 * 128;
            const int colb = kt * WTILE + g * 32 + 2 * (lane & 3);

            float c[4][4];
#pragma unroll
            for (int nt = 0; nt < 4; nt++) {
                float2 nn = *(const float2*)(wn + colb + nt * 8);
                c[nt][0] = nn.x + xnA; c[nt][1] = nn.y + xnA;
                c[nt][2] = nn.x + xnB; c[nt][3] = nn.y + xnB;
            }

            // single fp16 pass
#pragma unroll
            for (int kc32 = 0; kc32 < 2; kc32++) {
                const uint32_t ob = kc32 ? offb1 : offb0;
#pragma unroll
                for (int nt = 0; nt < 4; nt++) {
                    uint32_t bb[4];
                    ldsm4(bb, th + (uint32_t)nt * 1024 + ob);
                    mma16816(c[nt], ahi[kc32 * 2],     bb[0], bb[1]);
                    mma16816(c[nt], ahi[kc32 * 2 + 1], bb[2], bb[3]);
                }
            }

            // ---- top-2-of-group -> sorted top-4 running merge ----
            {
                uint32_t kA[8], kB[8];
#pragma unroll
                for (int nt = 0; nt < 4; nt++) {
                    const int c0 = colb + nt * 8;
                    kA[2*nt]   = fkey(c[nt][0], c0);
                    kA[2*nt+1] = fkey(c[nt][1], c0 + 1);
                    kB[2*nt]   = fkey(c[nt][2], c0);
                    kB[2*nt+1] = fkey(c[nt][3], c0 + 1);
                }
                uint32_t t1, t2;
                top2of8(kA, t1, t2);
                ins2into4(rA, t1, t2);
                top2of8(kB, t1, t2);
                ins2into4(rB, t1, t2);
            }
        }
        __syncthreads();   // compute on buf done -> safe to overwrite
        if (kt + 2 < KT) {
            uint32_t dst = smb + OFF_W + (uint32_t)buf * W_BUF;
            const char* src = g_wsw[kt + 2];
#pragma unroll
            for (int i = 0; i < 2; i++) {
                int off = (tid + i * BLOCK) * 16;
                cp16(dst + off, src + off);
            }
            asm volatile("cp.async.commit_group;" ::: "memory");
        }
    }

    // ---- merge sorted top-4 across the 4 lanes sharing each row ----
#pragma unroll
    for (int mm = 1; mm <= 2; mm <<= 1) {
        uint32_t oA[4], oB[4];
#pragma unroll
        for (int q = 0; q < 4; q++) {
            oA[q] = __shfl_xor_sync(0xFFFFFFFFu, rA[q], mm);
            oB[q] = __shfl_xor_sync(0xFFFFFFFFu, rB[q], mm);
        }
        mrg4(rA, oA);
        mrg4(rB, oB);
    }
    if ((lane & 3) == 0) {
        uint4* top = (uint4*)(sm + OFF_TOP);
        const int pA = warp * 16 + (lane >> 2);
        top[pA]     = make_uint4(rA[0], rA[1], rA[2], rA[3]);
        top[pA + 8] = make_uint4(rB[0], rB[1], rB[2], rB[3]);
    }
    __syncthreads();   // TOP visible; Y/W/WN regions now dead

    // ---- stage exact fp32 latents into smem (reuse Y/W/WN region) ----
    {
        const int p  = tid & 127;
        const int hh = tid >> 7;                 // 2 threads per point, 32 dims each
        const float* xp = x + (size_t)bimg * D * HW + hw0 + p;
        float* xs = (float*)(sm + OFF_XS);
#pragma unroll 8
        for (int dd = 0; dd < 32; dd++) {
            const int d = hh * 32 + dd;
            xs[p * XS_STRIDE + d] = xp[(size_t)d * HW];   // coalesced across lanes
        }
    }
    __syncthreads();

    // ---- cooperative quad rerank: 4 lanes per candidate row ----
    {
        const int q = lane >> 2;                 // quad id 0..7
        const int j = lane & 3;                  // lane within quad
        const float* xs = (const float*)(sm + OFF_XS);
        float* sc = (float*)(sm + OFF_RED);      // 512 candidate scores
        const uint4* top = (const uint4*)(sm + OFF_TOP);
#pragma unroll
        for (int it = 0; it < 8; it++) {
            const int cr = warp * 64 + it * 8 + q;   // candidate-row 0..511
            const int p  = cr >> 2;
            const int cc = cr & 3;
            uint4 t = top[p];
            uint32_t key = (cc == 0) ? t.x : (cc == 1) ? t.y : (cc == 2) ? t.z : t.w;
            const int wi = (int)(key & 1023u);
            const float4* wr = (const float4*)(w + (size_t)wi * D);
            const float*  xb = xs + p * XS_STRIDE;
            float s = 0.0f;
#pragma unroll
            for (int i = 0; i < 4; i++) {
                const int f4 = j + 4 * i;
                float4 a  = wr[f4];                          // 4 lanes: 64B consecutive
                float4 xv = *(const float4*)(xb + f4 * 4);
                s = fmaf(a.x, fmaf(-2.0f, xv.x, a.x), s);
                s = fmaf(a.y, fmaf(-2.0f, xv.y, a.y), s);
                s = fmaf(a.z, fmaf(-2.0f, xv.z, a.z), s);
                s = fmaf(a.w, fmaf(-2.0f, xv.w, a.w), s);
            }
            s += __shfl_xor_sync(0xFFFFFFFFu, s, 1);
            s += __shfl_xor_sync(0xFFFFFFFFu, s, 2);
            if (j == 0) sc[cr] = s;
        }
    }
    __syncthreads();

    // ---- finalize: min over 4 candidates with exact index tie-break ----
    int* sidx = (int*)(sm + OFF_IDX);
    if (tid < MTILE) {
        uint4 t = ((const uint4*)(sm + OFF_TOP))[tid];
        float4 s = *(const float4*)((const float*)(sm + OFF_RED) + tid * 4);
        int i0 = (int)(t.x & 1023u), i1 = (int)(t.y & 1023u);
        int i2 = (int)(t.z & 1023u), i3 = (int)(t.w & 1023u);
        float bs = s.x; int bi = i0;
        if (s.y < bs || (s.y == bs && i1 < bi)) { bs = s.y; bi = i1; }
        if (s.z < bs || (s.z == bs && i2 < bi)) { bs = s.z; bi = i2; }
        if (s.w < bs || (s.w == bs && i3 < bi)) { bs = s.w; bi = i3; }
        sidx[tid] = bi;
    }
    __syncthreads();

    // ---- coalesced gather of winning codewords ----
    {
        const float4* w4 = (const float4*)w;
        float4* o4 = (float4*)out;
        const size_t obase = (size_t)blockIdx.x * MTILE * (D / 4);
#pragma unroll 4
        for (int i = tid; i < MTILE * (D / 4); i += BLOCK) {
            const int p = i >> 4, d4 = i & 15;
            o4[obase + i] = w4[(size_t)sidx[p] * (D / 4) + d4];
        }
    }
}

extern "C" void kernel_launch(void* const* d_in, const int* in_sizes, int n_in,
                              void* d_out, int out_size)
{
    const float* x = (const float*)d_in[0];   // [64, 64, 32, 32]
    const float* w = (const float*)d_in[1];   // [1024, 64]
    float* out = (float*)d_out;               // [65536, 64]
    (void)in_sizes; (void)n_in; (void)out_size;

    vq_prep_kernel<<<128, 256>>>(w);
    cudaFuncSetAttribute(vq_hmma_kernel, cudaFuncAttributeMaxDynamicSharedMemorySize, SMEM_TOTAL);
    vq_hmma_kernel<<<65536 / MTILE, BLOCK, SMEM_TOTAL>>>(x, w, out);
}

// round 16
// speedup vs baseline: 1.4305x; 1.4305x over previous
#include <cuda_runtime.h>
#include <cuda_fp16.h>
#include <cstdint>

// VectorQuantizer: single-pass fp16 mma.sync screening (m16n8k16, fp32 acc)
// + sorted top-4 candidates + exact fp32 rerank.
// R13 = R9 base (WTILE=128, 3 CTAs/SM) + cooperative quad rerank
// (4 lanes per candidate row, x staged in smem at 16B-aligned stride 68).

#define D      64
#define K      1024
#define MTILE  128        // points per CTA (8 warps x 16 rows)
#define WTILE  128        // codewords per tile
#define KT     (K / WTILE)
#define BLOCK  256
#define HW     1024       // d-stride inside x

// ---- smem layout (bytes) ----
#define OFF_Y   0                 // 128 x 128B fp16   (reused by XS after loop)
#define OFF_W   16384             // 2 bufs x 16KB     (reused by XS after loop)
#define W_BUF   16384
#define OFF_WN  49152             // 1024 fp32 norms   (dead after loop)
#define OFF_XN  53248             // 2 x 128 fp32 partial ||x||^2
#define OFF_TOP 54272             // 128 x uint4 (sorted top-4 keys)  [live in rerank]
#define OFF_RED 56320             // 512 fp32 candidate scores (rerank)
#define OFF_IDX 58368             // 128 int
#define SMEM_TOTAL 58880

// rerank staging: fp32 latents, stride 68 floats = 272B (16B aligned per row)
#define OFF_XS    0
#define XS_STRIDE 68              // 128*68*4 = 34816 B, fits in dead Y+W region

#define SW(o) ((o) ^ (((o) >> 3) & 0x70))

// ---- global scratch: swizzled fp16 codebook tiles + norms ----
__device__ __align__(1024) static char  g_wsw[KT][WTILE * 128];
__device__ __align__(16)   static float g_wn[K];

static __device__ __forceinline__ uint32_t smem_u32(const void* p) {
    uint32_t a;
    asm("{ .reg .u64 t; cvta.to.shared.u64 t, %1; cvt.u32.u64 %0, t; }" : "=r"(a) : "l"(p));
    return a;
}
static __device__ __forceinline__ void cp16(uint32_t saddr, const void* g) {
    asm volatile("cp.async.cg.shared.global [%0], [%1], 16;"
                 :: "r"(saddr), "l"((size_t)__cvta_generic_to_global(g)) : "memory");
}
static __device__ __forceinline__ void ldsm4(uint32_t r[4], uint32_t addr) {
    asm volatile("ldmatrix.sync.aligned.m8n8.x4.shared.b16 {%0,%1,%2,%3}, [%4];"
                 : "=r"(r[0]), "=r"(r[1]), "=r"(r[2]), "=r"(r[3]) : "r"(addr));
}
static __device__ __forceinline__ void mma16816(float c[4], const uint32_t a[4],
                                                uint32_t b0, uint32_t b1) {
    asm volatile("mma.sync.aligned.m16n8k16.row.col.f32.f16.f16.f32 "
                 "{%0,%1,%2,%3}, {%4,%5,%6,%7}, {%8,%9}, {%0,%1,%2,%3};"
                 : "+f"(c[0]), "+f"(c[1]), "+f"(c[2]), "+f"(c[3])
                 : "r"(a[0]), "r"(a[1]), "r"(a[2]), "r"(a[3]), "r"(b0), "r"(b1));
}
static __device__ __forceinline__ uint32_t umn(uint32_t a, uint32_t b) { return a < b ? a : b; }
static __device__ __forceinline__ uint32_t umx(uint32_t a, uint32_t b) { return a > b ? a : b; }

// scores >= ~1 -> raw float bits order as u32. 13 mantissa bits + 10 index bits.
static __device__ __forceinline__ uint32_t fkey(float v, int col) {
    return (__float_as_uint(v) & 0xFFFFFC00u) | (uint32_t)col;
}
static __device__ __forceinline__ void mrg2(uint32_t& o1, uint32_t& o2,
                                            uint32_t a1, uint32_t a2,
                                            uint32_t b1, uint32_t b2) {
    o1 = umn(a1, b1);
    o2 = umn(umx(a1, b1), umn(a2, b2));
}
// sorted top-2 of 8 keys
static __device__ __forceinline__ void top2of8(const uint32_t k[8],
                                               uint32_t& t1, uint32_t& t2) {
    uint32_t a1 = umn(k[0], k[1]), a2 = umx(k[0], k[1]);
    uint32_t b1 = umn(k[2], k[3]), b2 = umx(k[2], k[3]);
    uint32_t c1 = umn(k[4], k[5]), c2 = umx(k[4], k[5]);
    uint32_t d1 = umn(k[6], k[7]), d2 = umx(k[6], k[7]);
    uint32_t e1, e2, f1, f2;
    mrg2(e1, e2, a1, a2, b1, b2);
    mrg2(f1, f2, c1, c2, d1, d2);
    mrg2(t1, t2, e1, e2, f1, f2);
}
// insert sorted pair (t1<=t2) into sorted-4 r[], keep lowest 4
static __device__ __forceinline__ void ins2into4(uint32_t r[4], uint32_t t1, uint32_t t2) {
    uint32_t m0 = r[0];
    uint32_t m1 = r[1];
    uint32_t m2 = umn(r[2], t2);
    uint32_t m3 = umn(r[3], t1);
    uint32_t s0 = umn(m0, m2), s2 = umx(m0, m2);
    uint32_t s1 = umn(m1, m3), s3 = umx(m1, m3);
    r[0] = umn(s0, s1); r[1] = umx(s0, s1);
    r[2] = umn(s2, s3); r[3] = umx(s2, s3);
}
// merge two sorted-4 lists, keep lowest 4
static __device__ __forceinline__ void mrg4(uint32_t r[4], const uint32_t b[4]) {
    uint32_t m0 = umn(r[0], b[3]);
    uint32_t m1 = umn(r[1], b[2]);
    uint32_t m2 = umn(r[2], b[1]);
    uint32_t m3 = umn(r[3], b[0]);
    uint32_t s0 = umn(m0, m2), s2 = umx(m0, m2);
    uint32_t s1 = umn(m1, m3), s3 = umx(m1, m3);
    r[0] = umn(s0, s1); r[1] = umx(s0, s1);
    r[2] = umn(s2, s3); r[3] = umx(s2, s3);
}

// ---------------- pre-kernel: convert codebook once ----------------
__global__ __launch_bounds__(256)
void vq_prep_kernel(const float* __restrict__ w)
{
    const int gid = blockIdx.x * 256 + threadIdx.x;   // 128 blocks -> 32768 threads
    {
        const int i  = gid;                           // pair index
        const int kr = i >> 5;                        // codeword 0..1023
        const int p  = i & 31;                        // pair within row
        float2 v = ((const float2*)w)[i];
        __half h0 = __float2half_rn(v.x), h1 = __float2half_rn(v.y);
        const int kt = kr >> 7, pr = kr & 127;
        uint32_t o = SW((uint32_t)(pr * 128 + p * 4));
        *(__half2*)(g_wsw[kt] + o) = __halves2half2(h0, h1);
    }
    if (gid < K) {
        const float4* wr = (const float4*)(w + (size_t)gid * D);
        float s = 0.0f;
#pragma unroll
        for (int q = 0; q < D / 4; q++) {
            float4 f = wr[q];
            s = fmaf(f.x, f.x, s); s = fmaf(f.y, f.y, s);
            s = fmaf(f.z, f.z, s); s = fmaf(f.w, f.w, s);
        }
        g_wn[gid] = s;
    }
}

// ---------------- main kernel ----------------
__global__ __launch_bounds__(BLOCK, 3)
void vq_hmma_kernel(const float* __restrict__ x,
                    const float* __restrict__ w,
                    float* __restrict__ out)
{
    extern __shared__ char sm[];
    const uint32_t smb = smem_u32(sm);
    const int tid  = threadIdx.x;
    const int lane = tid & 31;
    const int warp = tid >> 5;

    const int n0   = blockIdx.x * MTILE;
    const int bimg = n0 >> 10;
    const int hw0  = n0 & (HW - 1);

    // ---- prefetch: norms + tiles 0 and 1 ----
    cp16(smb + OFF_WN + tid * 16, g_wn + tid * 4);
#pragma unroll
    for (int i = 0; i < 4; i++) {
        int off = (tid + i * BLOCK) * 16;
        cp16(smb + OFF_W + off, g_wsw[0] + off);
    }
    asm volatile("cp.async.commit_group;" ::: "memory");
#pragma unroll
    for (int i = 0; i < 4; i++) {
        int off = (tid + i * BLOCK) * 16;
        cp16(smb + OFF_W + W_BUF + off, g_wsw[1] + off);
    }
    asm volatile("cp.async.commit_group;" ::: "memory");

    // ---- build Y = fp16(-2x) swizzled + partial ||x||^2 ----
    {
        const int p  = tid & 127;
        const int d0 = (tid >> 7) * 32;
        const float* xp = x + (size_t)bimg * D * HW + hw0 + p;
        char* y = sm + OFF_Y;
        const uint32_t rb = (uint32_t)p * 128;
        float xs = 0.0f;
#pragma unroll
        for (int dd = 0; dd < 32; dd += 2) {
            const int d = d0 + dd;
            float xv0 = xp[(size_t)d * HW];
            float xv1 = xp[(size_t)(d + 1) * HW];
            xs = fmaf(xv0, xv0, xs);
            xs = fmaf(xv1, xv1, xs);
            __half h0 = __float2half_rn(-2.0f * xv0);
            __half h1 = __float2half_rn(-2.0f * xv1);
            uint32_t o = SW(rb + (uint32_t)d * 2);
            *(__half2*)(y + o) = __halves2half2(h0, h1);
        }
        ((float*)(sm + OFF_XN))[(tid >> 7) * 128 + p] = xs;
    }
    __syncthreads();   // Y + xn partials visible

    // ---- per-lane row norms: xn + 1 ----
    float xnA, xnB;
    {
        const float* xpart = (const float*)(sm + OFF_XN);
        const int r0 = warp * 16 + (lane >> 2);
        xnA = xpart[r0] + xpart[128 + r0] + 1.0f;
        xnB = xpart[r0 + 8] + xpart[128 + r0 + 8] + 1.0f;
    }

    // ---- A fragments (this warp's 16 points x 64 d) in regs ----
    uint32_t ahi[4][4];
    const int lr = lane & 7;
    const int mI = lane >> 3;
    {
        const uint32_t arow = (uint32_t)(warp * 16 + (mI & 1) * 8 + lr) * 128;
#pragma unroll
        for (int kc = 0; kc < 4; kc++) {
            uint32_t ch = (uint32_t)((kc * 2 + (mI >> 1)) ^ lr) * 16;
            ldsm4(ahi[kc], smb + OFF_Y + arow + ch);
        }
    }

    const uint32_t offb0 = (uint32_t)lr * 128 + (uint32_t)(mI ^ lr) * 16;       // k-chunks 0-3
    const uint32_t offb1 = (uint32_t)lr * 128 + (uint32_t)((4 + mI) ^ lr) * 16; // k-chunks 4-7
    const float* wn = (const float*)(sm + OFF_WN);

    uint32_t rA[4] = {0xFFFFFFFFu, 0xFFFFFFFFu, 0xFFFFFFFFu, 0xFFFFFFFFu};
    uint32_t rB[4] = {0xFFFFFFFFu, 0xFFFFFFFFu, 0xFFFFFFFFu, 0xFFFFFFFFu};

#pragma unroll 1
    for (int kt = 0; kt < KT; kt++) {
        const int buf = kt & 1;
        if (kt < KT - 1) asm volatile("cp.async.wait_group 1;" ::: "memory");
        else             asm volatile("cp.async.wait_group 0;" ::: "memory");
        __syncthreads();   // tile visible; prior compute on buf done

        const uint32_t gb = smb + OFF_W + (uint32_t)buf * W_BUF;

#pragma unroll 1
        for (int g = 0; g < WTILE / 32; g++) {
            const uint32_t th = gb + (uint32_t)g * 32 * 128;
            const int colb = kt * WTILE + g * 32 + 2 * (lane & 3);

            float c[4][4];
#pragma unroll
            for (int nt = 0; nt < 4; nt++) {
                float2 nn = *(const float2*)(wn + colb + nt * 8);
                c[nt][0] = nn.x + xnA; c[nt][1] = nn.y + xnA;
                c[nt][2] = nn.x + xnB; c[nt][3] = nn.y + xnB;
            }

            // single fp16 pass
#pragma unroll
            for (int kc32 = 0; kc32 < 2; kc32++) {
                const uint32_t ob = kc32 ? offb1 : offb0;
#pragma unroll
                for (int nt = 0; nt < 4; nt++) {
                    uint32_t bb[4];
                    ldsm4(bb, th + (uint32_t)nt * 1024 + ob);
                    mma16816(c[nt], ahi[kc32 * 2],     bb[0], bb[1]);
                    mma16816(c[nt], ahi[kc32 * 2 + 1], bb[2], bb[3]);
                }
            }

            // ---- top-2-of-group -> sorted top-4 running merge ----
            {
                uint32_t kA[8], kB[8];
#pragma unroll
                for (int nt = 0; nt < 4; nt++) {
                    const int c0 = colb + nt * 8;
                    kA[2*nt]   = fkey(c[nt][0], c0);
                    kA[2*nt+1] = fkey(c[nt][1], c0 + 1);
                    kB[2*nt]   = fkey(c[nt][2], c0);
                    kB[2*nt+1] = fkey(c[nt][3], c0 + 1);
                }
                uint32_t t1, t2;
                top2of8(kA, t1, t2);
                ins2into4(rA, t1, t2);
                top2of8(kB, t1, t2);
                ins2into4(rB, t1, t2);
            }
        }
        __syncthreads();   // compute on buf done -> safe to overwrite
        if (kt + 2 < KT) {
            uint32_t dst = smb + OFF_W + (uint32_t)buf * W_BUF;
            const char* src = g_wsw[kt + 2];
#pragma unroll
            for (int i = 0; i < 4; i++) {
                int off = (tid + i * BLOCK) * 16;
                cp16(dst + off, src + off);
            }
            asm volatile("cp.async.commit_group;" ::: "memory");
        }
    }

    // ---- merge sorted top-4 across the 4 lanes sharing each row ----
#pragma unroll
    for (int mm = 1; mm <= 2; mm <<= 1) {
        uint32_t oA[4], oB[4];
#pragma unroll
        for (int q = 0; q < 4; q++) {
            oA[q] = __shfl_xor_sync(0xFFFFFFFFu, rA[q], mm);
            oB[q] = __shfl_xor_sync(0xFFFFFFFFu, rB[q], mm);
        }
        mrg4(rA, oA);
        mrg4(rB, oB);
    }
    if ((lane & 3) == 0) {
        uint4* top = (uint4*)(sm + OFF_TOP);
        const int pA = warp * 16 + (lane >> 2);
        top[pA]     = make_uint4(rA[0], rA[1], rA[2], rA[3]);
        top[pA + 8] = make_uint4(rB[0], rB[1], rB[2], rB[3]);
    }
    __syncthreads();   // TOP visible; Y/W/WN regions now dead

    // ---- stage exact fp32 latents into smem (stride 68: rows 16B-aligned) ----
    {
        const int p  = tid & 127;
        const int hh = tid >> 7;                 // 2 threads per point, 32 dims each
        const float* xp = x + (size_t)bimg * D * HW + hw0 + p;
        float* xs = (float*)(sm + OFF_XS);
#pragma unroll
        for (int dd = 0; dd < 32; dd++) {
            const int d = hh * 32 + dd;
            xs[p * XS_STRIDE + d] = xp[(size_t)d * HW];   // gmem coalesced across lanes
        }
    }
    __syncthreads();

    // ---- cooperative quad rerank: 4 lanes per candidate row ----
    {
        const int q = lane >> 2;                 // quad id 0..7
        const int j = lane & 3;                  // lane within quad
        const float* xs = (const float*)(sm + OFF_XS);
        float* sc = (float*)(sm + OFF_RED);      // 512 candidate scores
        const uint4* top = (const uint4*)(sm + OFF_TOP);
#pragma unroll
        for (int it = 0; it < 8; it++) {
            const int cr = warp * 64 + it * 8 + q;   // candidate-row 0..511
            const int p  = cr >> 2;
            const int cc = cr & 3;
            uint4 t = top[p];
            uint32_t key = (cc == 0) ? t.x : (cc == 1) ? t.y : (cc == 2) ? t.z : t.w;
            const int wi = (int)(key & 1023u);
            const float4* wr = (const float4*)(w + (size_t)wi * D);
            const float*  xb = xs + p * XS_STRIDE;
            float s = 0.0f;
#pragma unroll
            for (int i = 0; i < 4; i++) {
                const int f4 = j + 4 * i;
                float4 a  = wr[f4];                          // quad reads 64B consecutive
                float4 xv = *(const float4*)(xb + f4 * 4);   // 16B-aligned (stride 68)
                s = fmaf(a.x, fmaf(-2.0f, xv.x, a.x), s);
                s = fmaf(a.y, fmaf(-2.0f, xv.y, a.y), s);
                s = fmaf(a.z, fmaf(-2.0f, xv.z, a.z), s);
                s = fmaf(a.w, fmaf(-2.0f, xv.w, a.w), s);
            }
            s += __shfl_xor_sync(0xFFFFFFFFu, s, 1);
            s += __shfl_xor_sync(0xFFFFFFFFu, s, 2);
            if (j == 0) sc[cr] = s;
        }
    }
    __syncthreads();

    // ---- finalize: min over 4 candidates with exact index tie-break ----
    int* sidx = (int*)(sm + OFF_IDX);
    if (tid < MTILE) {
        uint4 t = ((const uint4*)(sm + OFF_TOP))[tid];
        float4 s = *(const float4*)((const float*)(sm + OFF_RED) + tid * 4);
        int i0 = (int)(t.x & 1023u), i1 = (int)(t.y & 1023u);
        int i2 = (int)(t.z & 1023u), i3 = (int)(t.w & 1023u);
        float bs = s.x; int bi = i0;
        if (s.y < bs || (s.y == bs && i1 < bi)) { bs = s.y; bi = i1; }
        if (s.z < bs || (s.z == bs && i2 < bi)) { bs = s.z; bi = i2; }
        if (s.w < bs || (s.w == bs && i3 < bi)) { bs = s.w; bi = i3; }
        sidx[tid] = bi;
    }
    __syncthreads();

    // ---- coalesced gather of winning codewords ----
    {
        const float4* w4 = (const float4*)w;
        float4* o4 = (float4*)out;
        const size_t obase = (size_t)blockIdx.x * MTILE * (D / 4);
#pragma unroll 4
        for (int i = tid; i < MTILE * (D / 4); i += BLOCK) {
            const int p = i >> 4, d4 = i & 15;
            o4[obase + i] = w4[(size_t)sidx[p] * (D / 4) + d4];
        }
    }
}

extern "C" void kernel_launch(void* const* d_in, const int* in_sizes, int n_in,
                              void* d_out, int out_size)
{
    const float* x = (const float*)d_in[0];   // [64, 64, 32, 32]
    const float* w = (const float*)d_in[1];   // [1024, 64]
    float* out = (float*)d_out;               // [65536, 64]
    (void)in_sizes; (void)n_in; (void)out_size;

    vq_prep_kernel<<<128, 256>>>(w);
    cudaFuncSetAttribute(vq_hmma_kernel, cudaFuncAttributeMaxDynamicSharedMemorySize, SMEM_TOTAL);
    vq_hmma_kernel<<<65536 / MTILE, BLOCK, SMEM_TOTAL>>>(x, w, out);
}

// round 17
// speedup vs baseline: 1.5361x; 1.0738x over previous
#include <cuda_runtime.h>
#include <cuda_fp16.h>
#include <cstdint>

// VectorQuantizer: single-pass fp16 mma.sync screening (m16n8k16, fp32 acc)
// + sorted top-4 candidates + exact fp32 quad rerank.
// R14: MTILE=256, 32 rows/warp (2 m-tiles) -> 4 HMMA per B-LDSM,
// 2 CTAs/SM, grid=256 = single wave.

#define D      64
#define K      1024
#define MTILE  256        // points per CTA (8 warps x 32 rows)
#define WTILE  128        // codewords per tile
#define KT     (K / WTILE)
#define BLOCK  256
#define HW     1024       // d-stride inside x

// ---- smem layout (bytes) ----
#define OFF_Y   0                 // 256 x 128B fp16 (dead after A-frag load)
#define OFF_W   32768             // 2 bufs x 16KB   (dead after mainloop)
#define W_BUF   16384
#define OFF_WN  65536             // 1024 fp32 norms (dead after mainloop)
#define OFF_XN  69632             // 256 fp32 ||x||^2+1 (dead after xn read)
#define OFF_TOP 70656             // 256 x uint4 sorted top-4 keys [live in rerank]
#define OFF_RED 74752             // 1024 fp32 candidate scores
#define OFF_IDX 78848             // 256 int
#define SMEM_TOTAL 79872

// rerank staging: fp32 latents, stride 68 floats = 272B (16B aligned rows)
// 256*68*4 = 69632 B == exactly the dead Y+W+WN region [0, OFF_XN)
#define OFF_XS    0
#define XS_STRIDE 68

#define SW(o) ((o) ^ (((o) >> 3) & 0x70))

// ---- global scratch: swizzled fp16 codebook tiles + norms ----
__device__ __align__(1024) static char  g_wsw[KT][WTILE * 128];
__device__ __align__(16)   static float g_wn[K];

static __device__ __forceinline__ uint32_t smem_u32(const void* p) {
    uint32_t a;
    asm("{ .reg .u64 t; cvta.to.shared.u64 t, %1; cvt.u32.u64 %0, t; }" : "=r"(a) : "l"(p));
    return a;
}
static __device__ __forceinline__ void cp16(uint32_t saddr, const void* g) {
    asm volatile("cp.async.cg.shared.global [%0], [%1], 16;"
                 :: "r"(saddr), "l"((size_t)__cvta_generic_to_global(g)) : "memory");
}
static __device__ __forceinline__ void ldsm4(uint32_t r[4], uint32_t addr) {
    asm volatile("ldmatrix.sync.aligned.m8n8.x4.shared.b16 {%0,%1,%2,%3}, [%4];"
                 : "=r"(r[0]), "=r"(r[1]), "=r"(r[2]), "=r"(r[3]) : "r"(addr));
}
static __device__ __forceinline__ void mma16816(float c[4], const uint32_t a[4],
                                                uint32_t b0, uint32_t b1) {
    asm volatile("mma.sync.aligned.m16n8k16.row.col.f32.f16.f16.f32 "
                 "{%0,%1,%2,%3}, {%4,%5,%6,%7}, {%8,%9}, {%0,%1,%2,%3};"
                 : "+f"(c[0]), "+f"(c[1]), "+f"(c[2]), "+f"(c[3])
                 : "r"(a[0]), "r"(a[1]), "r"(a[2]), "r"(a[3]), "r"(b0), "r"(b1));
}
static __device__ __forceinline__ uint32_t umn(uint32_t a, uint32_t b) { return a < b ? a : b; }
static __device__ __forceinline__ uint32_t umx(uint32_t a, uint32_t b) { return a > b ? a : b; }

// scores >= ~1 -> raw float bits order as u32. 13 mantissa bits + 10 index bits.
static __device__ __forceinline__ uint32_t fkey(float v, int col) {
    return (__float_as_uint(v) & 0xFFFFFC00u) | (uint32_t)col;
}
// sorted top-2 of 4 keys
static __device__ __forceinline__ void top2of4(uint32_t a, uint32_t b,
                                               uint32_t c, uint32_t d,
                                               uint32_t& t1, uint32_t& t2) {
    uint32_t p1 = umn(a, b), p2 = umx(a, b);
    uint32_t q1 = umn(c, d), q2 = umx(c, d);
    t1 = umn(p1, q1);
    t2 = umn(umx(p1, q1), umn(p2, q2));
}
// insert sorted pair (t1<=t2) into sorted-4 r[], keep lowest 4
static __device__ __forceinline__ void ins2into4(uint32_t r[4], uint32_t t1, uint32_t t2) {
    uint32_t m0 = r[0];
    uint32_t m1 = r[1];
    uint32_t m2 = umn(r[2], t2);
    uint32_t m3 = umn(r[3], t1);
    uint32_t s0 = umn(m0, m2), s2 = umx(m0, m2);
    uint32_t s1 = umn(m1, m3), s3 = umx(m1, m3);
    r[0] = umn(s0, s1); r[1] = umx(s0, s1);
    r[2] = umn(s2, s3); r[3] = umx(s2, s3);
}
// merge two sorted-4 lists, keep lowest 4
static __device__ __forceinline__ void mrg4(uint32_t r[4], const uint32_t b[4]) {
    uint32_t m0 = umn(r[0], b[3]);
    uint32_t m1 = umn(r[1], b[2]);
    uint32_t m2 = umn(r[2], b[1]);
    uint32_t m3 = umn(r[3], b[0]);
    uint32_t s0 = umn(m0, m2), s2 = umx(m0, m2);
    uint32_t s1 = umn(m1, m3), s3 = umx(m1, m3);
    r[0] = umn(s0, s1); r[1] = umx(s0, s1);
    r[2] = umn(s2, s3); r[3] = umx(s2, s3);
}

// ---------------- pre-kernel: convert codebook once ----------------
__global__ __launch_bounds__(256)
void vq_prep_kernel(const float* __restrict__ w)
{
    const int gid = blockIdx.x * 256 + threadIdx.x;   // 128 blocks -> 32768 threads
    {
        const int i  = gid;                           // pair index
        const int kr = i >> 5;                        // codeword 0..1023
        const int p  = i & 31;                        // pair within row
        float2 v = ((const float2*)w)[i];
        __half h0 = __float2half_rn(v.x), h1 = __float2half_rn(v.y);
        const int kt = kr >> 7, pr = kr & 127;
        uint32_t o = SW((uint32_t)(pr * 128 + p * 4));
        *(__half2*)(g_wsw[kt] + o) = __halves2half2(h0, h1);
    }
    if (gid < K) {
        const float4* wr = (const float4*)(w + (size_t)gid * D);
        float s = 0.0f;
#pragma unroll
        for (int q = 0; q < D / 4; q++) {
            float4 f = wr[q];
            s = fmaf(f.x, f.x, s); s = fmaf(f.y, f.y, s);
            s = fmaf(f.z, f.z, s); s = fmaf(f.w, f.w, s);
        }
        g_wn[gid] = s;
    }
}

// ---------------- main kernel ----------------
__global__ __launch_bounds__(BLOCK, 2)
void vq_hmma_kernel(const float* __restrict__ x,
                    const float* __restrict__ w,
                    float* __restrict__ out)
{
    extern __shared__ char sm[];
    const uint32_t smb = smem_u32(sm);
    const int tid  = threadIdx.x;
    const int lane = tid & 31;
    const int warp = tid >> 5;

    const int n0   = blockIdx.x * MTILE;
    const int bimg = n0 >> 10;
    const int hw0  = n0 & (HW - 1);

    // ---- prefetch: norms + tiles 0 and 1 ----
    cp16(smb + OFF_WN + tid * 16, g_wn + tid * 4);
#pragma unroll
    for (int i = 0; i < 4; i++) {
        int off = (tid + i * BLOCK) * 16;
        cp16(smb + OFF_W + off, g_wsw[0] + off);
    }
    asm volatile("cp.async.commit_group;" ::: "memory");
#pragma unroll
    for (int i = 0; i < 4; i++) {
        int off = (tid + i * BLOCK) * 16;
        cp16(smb + OFF_W + W_BUF + off, g_wsw[1] + off);
    }
    asm volatile("cp.async.commit_group;" ::: "memory");

    // ---- build Y = fp16(-2x) swizzled + ||x||^2 (one point per thread) ----
    {
        const float* xp = x + (size_t)bimg * D * HW + hw0 + tid;
        char* y = sm + OFF_Y;
        const uint32_t rb = (uint32_t)tid * 128;
        float xs = 0.0f;
#pragma unroll
        for (int d = 0; d < D; d += 2) {
            float xv0 = xp[(size_t)d * HW];
            float xv1 = xp[(size_t)(d + 1) * HW];
            xs = fmaf(xv0, xv0, xs);
            xs = fmaf(xv1, xv1, xs);
            __half h0 = __float2half_rn(-2.0f * xv0);
            __half h1 = __float2half_rn(-2.0f * xv1);
            uint32_t o = SW(rb + (uint32_t)d * 2);
            *(__half2*)(y + o) = __halves2half2(h0, h1);
        }
        ((float*)(sm + OFF_XN))[tid] = xs + 1.0f;   // scores >= ~1
    }
    __syncthreads();   // Y + XN visible

    // ---- per-lane row norms: this lane owns 4 rows (2 m-tiles x 2 halves) ----
    float xn[2][2];
    {
        const float* xnp = (const float*)(sm + OFF_XN);
        const int r0 = warp * 32 + (lane >> 2);
        xn[0][0] = xnp[r0];      xn[0][1] = xnp[r0 + 8];
        xn[1][0] = xnp[r0 + 16]; xn[1][1] = xnp[r0 + 24];
    }

    // ---- A fragments: 2 m-tiles x 4 k-chunks ----
    uint32_t ahi[2][4][4];
    const int lr = lane & 7;
    const int mI = lane >> 3;
#pragma unroll
    for (int m = 0; m < 2; m++) {
        const uint32_t arow = (uint32_t)(warp * 32 + m * 16 + (mI & 1) * 8 + lr) * 128;
#pragma unroll
        for (int kc = 0; kc < 4; kc++) {
            uint32_t ch = (uint32_t)((kc * 2 + (mI >> 1)) ^ lr) * 16;
            ldsm4(ahi[m][kc], smb + OFF_Y + arow + ch);
        }
    }

    const uint32_t offb0 = (uint32_t)lr * 128 + (uint32_t)(mI ^ lr) * 16;       // k-chunks 0-3
    const uint32_t offb1 = (uint32_t)lr * 128 + (uint32_t)((4 + mI) ^ lr) * 16; // k-chunks 4-7
    const float* wn = (const float*)(sm + OFF_WN);

    uint32_t r4[2][2][4];
#pragma unroll
    for (int m = 0; m < 2; m++)
#pragma unroll
        for (int u = 0; u < 2; u++)
#pragma unroll
            for (int q = 0; q < 4; q++) r4[m][u][q] = 0xFFFFFFFFu;

#pragma unroll 1
    for (int kt = 0; kt < KT; kt++) {
        const int buf = kt & 1;
        if (kt < KT - 1) asm volatile("cp.async.wait_group 1;" ::: "memory");
        else             asm volatile("cp.async.wait_group 0;" ::: "memory");
        __syncthreads();   // tile visible; prior compute on buf done

        const uint32_t gb = smb + OFF_W + (uint32_t)buf * W_BUF;

#pragma unroll 1
        for (int g = 0; g < WTILE / 16; g++) {           // 16 codewords per group
            const uint32_t th = gb + (uint32_t)g * 2048;
            const int colb = kt * WTILE + g * 16 + 2 * (lane & 3);

            float c[2][2][4];
#pragma unroll
            for (int nt = 0; nt < 2; nt++) {
                float2 nn = *(const float2*)(wn + colb + nt * 8);
#pragma unroll
                for (int m = 0; m < 2; m++) {
                    c[m][nt][0] = nn.x + xn[m][0]; c[m][nt][1] = nn.y + xn[m][0];
                    c[m][nt][2] = nn.x + xn[m][1]; c[m][nt][3] = nn.y + xn[m][1];
                }
            }

            // single fp16 pass: each B-LDSM feeds 4 HMMA (2 m-tiles)
#pragma unroll
            for (int kc32 = 0; kc32 < 2; kc32++) {
                const uint32_t ob = kc32 ? offb1 : offb0;
#pragma unroll
                for (int nt = 0; nt < 2; nt++) {
                    uint32_t bb[4];
                    ldsm4(bb, th + (uint32_t)nt * 1024 + ob);
#pragma unroll
                    for (int m = 0; m < 2; m++) {
                        mma16816(c[m][nt], ahi[m][kc32 * 2],     bb[0], bb[1]);
                        mma16816(c[m][nt], ahi[m][kc32 * 2 + 1], bb[2], bb[3]);
                    }
                }
            }

            // ---- top-2-of-4 per owned row -> sorted top-4 running merge ----
#pragma unroll
            for (int m = 0; m < 2; m++) {
                uint32_t t1, t2;
                top2of4(fkey(c[m][0][0], colb),     fkey(c[m][0][1], colb + 1),
                        fkey(c[m][1][0], colb + 8), fkey(c[m][1][1], colb + 9), t1, t2);
                ins2into4(r4[m][0], t1, t2);
                top2of4(fkey(c[m][0][2], colb),     fkey(c[m][0][3], colb + 1),
                        fkey(c[m][1][2], colb + 8), fkey(c[m][1][3], colb + 9), t1, t2);
                ins2into4(r4[m][1], t1, t2);
            }
        }
        __syncthreads();   // compute on buf done -> safe to overwrite
        if (kt + 2 < KT) {
            uint32_t dst = smb + OFF_W + (uint32_t)buf * W_BUF;
            const char* src = g_wsw[kt + 2];
#pragma unroll
            for (int i = 0; i < 4; i++) {
                int off = (tid + i * BLOCK) * 16;
                cp16(dst + off, src + off);
            }
            asm volatile("cp.async.commit_group;" ::: "memory");
        }
    }

    // ---- merge sorted top-4 across the 4 lanes sharing each row ----
#pragma unroll
    for (int mm = 1; mm <= 2; mm <<= 1) {
#pragma unroll
        for (int m = 0; m < 2; m++)
#pragma unroll
            for (int u = 0; u < 2; u++) {
                uint32_t o4[4];
#pragma unroll
                for (int q = 0; q < 4; q++)
                    o4[q] = __shfl_xor_sync(0xFFFFFFFFu, r4[m][u][q], mm);
                mrg4(r4[m][u], o4);
            }
    }
    if ((lane & 3) == 0) {
        uint4* top = (uint4*)(sm + OFF_TOP);
        const int rb = warp * 32 + (lane >> 2);
#pragma unroll
        for (int m = 0; m < 2; m++)
#pragma unroll
            for (int u = 0; u < 2; u++)
                top[rb + m * 16 + u * 8] =
                    make_uint4(r4[m][u][0], r4[m][u][1], r4[m][u][2], r4[m][u][3]);
    }
    __syncthreads();   // TOP visible; Y/W/WN/XN regions now dead

    // ---- stage exact fp32 latents into smem (stride 68: rows 16B-aligned) ----
    {
        const float* xp = x + (size_t)bimg * D * HW + hw0 + tid;
        float* xs = (float*)(sm + OFF_XS);
#pragma unroll 8
        for (int d = 0; d < D; d++)
            xs[tid * XS_STRIDE + d] = xp[(size_t)d * HW];   // gmem coalesced across lanes
    }
    __syncthreads();

    // ---- cooperative quad rerank: 4 lanes per candidate row, 1024 rows ----
    {
        const int q = lane >> 2;                 // quad id 0..7
        const int j = lane & 3;                  // lane within quad
        const float* xs = (const float*)(sm + OFF_XS);
        float* sc = (float*)(sm + OFF_RED);      // 1024 candidate scores
        const uint4* top = (const uint4*)(sm + OFF_TOP);
#pragma unroll
        for (int it = 0; it < 16; it++) {
            const int cr = warp * 128 + it * 8 + q;  // candidate-row 0..1023
            const int p  = cr >> 2;
            const int cc = cr & 3;
            uint4 t = top[p];
            uint32_t key = (cc == 0) ? t.x : (cc == 1) ? t.y : (cc == 2) ? t.z : t.w;
            const int wi = (int)(key & 1023u);
            const float4* wr = (const float4*)(w + (size_t)wi * D);
            const float*  xb = xs + p * XS_STRIDE;
            float s = 0.0f;
#pragma unroll
            for (int i = 0; i < 4; i++) {
                const int f4 = j + 4 * i;
                float4 a  = wr[f4];                          // quad reads 64B consecutive
                float4 xv = *(const float4*)(xb + f4 * 4);   // 16B-aligned (stride 68)
                s = fmaf(a.x, fmaf(-2.0f, xv.x, a.x), s);
                s = fmaf(a.y, fmaf(-2.0f, xv.y, a.y), s);
                s = fmaf(a.z, fmaf(-2.0f, xv.z, a.z), s);
                s = fmaf(a.w, fmaf(-2.0f, xv.w, a.w), s);
            }
            s += __shfl_xor_sync(0xFFFFFFFFu, s, 1);
            s += __shfl_xor_sync(0xFFFFFFFFu, s, 2);
            if (j == 0) sc[cr] = s;
        }
    }
    __syncthreads();

    // ---- finalize: min over 4 candidates with exact index tie-break ----
    int* sidx = (int*)(sm + OFF_IDX);
    {
        uint4 t = ((const uint4*)(sm + OFF_TOP))[tid];
        float4 s = *(const float4*)((const float*)(sm + OFF_RED) + tid * 4);
        int i0 = (int)(t.x & 1023u), i1 = (int)(t.y & 1023u);
        int i2 = (int)(t.z & 1023u), i3 = (int)(t.w & 1023u);
        float bs = s.x; int bi = i0;
        if (s.y < bs || (s.y == bs && i1 < bi)) { bs = s.y; bi = i1; }
        if (s.z < bs || (s.z == bs && i2 < bi)) { bs = s.z; bi = i2; }
        if (s.w < bs || (s.w == bs && i3 < bi)) { bs = s.w; bi = i3; }
        sidx[tid] = bi;
    }
    __syncthreads();

    // ---- coalesced gather of winning codewords ----
    {
        const float4* w4 = (const float4*)w;
        float4* o4 = (float4*)out;
        const size_t obase = (size_t)blockIdx.x * MTILE * (D / 4);
#pragma unroll 4
        for (int i = tid; i < MTILE * (D / 4); i += BLOCK) {
            const int p = i >> 4, d4 = i & 15;
            o4[obase + i] = w4[(size_t)sidx[p] * (D / 4) + d4];
        }
    }
}

extern "C" void kernel_launch(void* const* d_in, const int* in_sizes, int n_in,
                              void* d_out, int out_size)
{
    const float* x = (const float*)d_in[0];   // [64, 64, 32, 32]
    const float* w = (const float*)d_in[1];   // [1024, 64]
    float* out = (float*)d_out;               // [65536, 64]
    (void)in_sizes; (void)n_in; (void)out_size;

    vq_prep_kernel<<<128, 256>>>(w);
    cudaFuncSetAttribute(vq_hmma_kernel, cudaFuncAttributeMaxDynamicSharedMemorySize, SMEM_TOTAL);
    vq_hmma_kernel<<<65536 / MTILE, BLOCK, SMEM_TOTAL>>>(x, w, out);
}